// round 1
// baseline (speedup 1.0000x reference)
#include <cuda_runtime.h>
#include <cstdint>

#define B_    128
#define T_    32
#define DIN   1536
#define HID   1024
#define NCAT  32

// Scratch (device globals — allocation is forbidden)
__device__ float g_hidden[B_ * T_ * HID];   // 16 MB fp32 hidden activations
__device__ int   g_perm[B_];                // batches sorted by category

// ---------------------------------------------------------------------------
// Pre-pass: counting sort of batch indices by category (128 elems, trivial).
// Gives L2 temporal locality: same-category CTAs run adjacently and share
// their weight tiles in L2 instead of re-reading HBM per batch.
// ---------------------------------------------------------------------------
__global__ void build_perm_kernel(const int* __restrict__ cat_ids) {
    if (threadIdx.x == 0 && blockIdx.x == 0) {
        int cnt[NCAT];
        #pragma unroll
        for (int c = 0; c < NCAT; c++) cnt[c] = 0;
        for (int i = 0; i < B_; i++) cnt[cat_ids[i]]++;
        int off[NCAT]; int s = 0;
        #pragma unroll
        for (int c = 0; c < NCAT; c++) { off[c] = s; s += cnt[c]; }
        for (int i = 0; i < B_; i++) {
            int c = cat_ids[i];
            g_perm[off[c]++] = i;
        }
    }
}

__device__ __forceinline__ uint32_t f2tf32(float f) {
    uint32_t r;
    asm("cvt.rna.tf32.f32 %0, %1;" : "=r"(r) : "f"(f));
    return r;
}

// ---------------------------------------------------------------------------
// One layer: out(B,T,1024) = act( in(B,T,KDIM) @ W[cat](KDIM,1024) + b[cat] )
// Block: 32x64 output tile (one batch = 32 rows), 256 threads = 8 warps in a
// 2(M) x 4(N) layout; each warp owns a 16x16 subtile via 2x m16n8k8 tf32 mma.
// ---------------------------------------------------------------------------
template <int KDIM, bool RELU, bool IN_SCRATCH, bool OUT_SCRATCH>
__global__ __launch_bounds__(256)
void catmlp_gemm(const float* __restrict__ gin,
                 const float* __restrict__ W,     // (C, KDIM, 1024)
                 const float* __restrict__ bias,  // (C, 1024)
                 const int*   __restrict__ cat_ids,
                 float* __restrict__ gout)
{
    constexpr int NOUT = 1024;
    const int batch = g_perm[blockIdx.x];
    const int n0    = blockIdx.y * 64;
    const int c     = cat_ids[batch];

    const float* A_in = (IN_SCRATCH ? g_hidden : gin) + (size_t)batch * T_ * KDIM;
    const float* Bw   = W + (size_t)c * KDIM * NOUT;

    __shared__ uint32_t As[32][33];   // [row][k]  (+1 pad)
    __shared__ uint32_t Bs[32][68];   // [k][n]    (+4 pad)

    const int tid  = threadIdx.x;
    const int wid  = tid >> 5;
    const int lane = tid & 31;
    const int wm   = (wid >> 2) << 4;   // warp row offset   (0 / 16)
    const int wn   = (wid & 3) << 4;    // warp col offset   (0/16/32/48)
    const int lg   = lane >> 2;         // lane / 4
    const int lr   = lane & 3;          // lane % 4

    float acc[2][4] = {{0.f,0.f,0.f,0.f},{0.f,0.f,0.f,0.f}};

    for (int k0 = 0; k0 < KDIM; k0 += 32) {
        // Stage A tile: 32 rows x 32 k  (1024 floats, 4/thread, float4)
        {
            const int r  = tid >> 3;
            const int kc = (tid & 7) << 2;
            float4 v = *reinterpret_cast<const float4*>(A_in + (size_t)r * KDIM + k0 + kc);
            As[r][kc + 0] = f2tf32(v.x);
            As[r][kc + 1] = f2tf32(v.y);
            As[r][kc + 2] = f2tf32(v.z);
            As[r][kc + 3] = f2tf32(v.w);
        }
        // Stage B tile: 32 k x 64 n  (2048 floats, 8/thread, 2x float4)
        #pragma unroll
        for (int it = 0; it < 2; it++) {
            const int idx = tid + it * 256;
            const int r   = idx >> 4;
            const int vc  = (idx & 15) << 2;
            float4 v = *reinterpret_cast<const float4*>(Bw + (size_t)(k0 + r) * NOUT + n0 + vc);
            Bs[r][vc + 0] = f2tf32(v.x);
            Bs[r][vc + 1] = f2tf32(v.y);
            Bs[r][vc + 2] = f2tf32(v.z);
            Bs[r][vc + 3] = f2tf32(v.w);
        }
        __syncthreads();

        #pragma unroll
        for (int ks = 0; ks < 32; ks += 8) {
            uint32_t a0 = As[wm + lg     ][ks + lr    ];
            uint32_t a1 = As[wm + lg + 8 ][ks + lr    ];
            uint32_t a2 = As[wm + lg     ][ks + lr + 4];
            uint32_t a3 = As[wm + lg + 8 ][ks + lr + 4];
            #pragma unroll
            for (int nt = 0; nt < 2; nt++) {
                uint32_t b0 = Bs[ks + lr    ][wn + nt * 8 + lg];
                uint32_t b1 = Bs[ks + lr + 4][wn + nt * 8 + lg];
                asm volatile(
                    "mma.sync.aligned.m16n8k8.row.col.f32.tf32.tf32.f32 "
                    "{%0,%1,%2,%3}, {%4,%5,%6,%7}, {%8,%9}, {%0,%1,%2,%3};"
                    : "+f"(acc[nt][0]), "+f"(acc[nt][1]),
                      "+f"(acc[nt][2]), "+f"(acc[nt][3])
                    : "r"(a0), "r"(a1), "r"(a2), "r"(a3),
                      "r"(b0), "r"(b1));
            }
        }
        __syncthreads();
    }

    // Epilogue: + bias, optional ReLU, write fp32
    const float* bv = bias + (size_t)c * NOUT + n0;
    float* O = (OUT_SCRATCH ? g_hidden : gout) + (size_t)batch * T_ * NOUT + n0;
    const int row = wm + lg;
    #pragma unroll
    for (int nt = 0; nt < 2; nt++) {
        const int col = wn + nt * 8 + (lr << 1);
        float bc0 = bv[col], bc1 = bv[col + 1];
        float v0 = acc[nt][0] + bc0;
        float v1 = acc[nt][1] + bc1;
        float v2 = acc[nt][2] + bc0;
        float v3 = acc[nt][3] + bc1;
        if (RELU) {
            v0 = fmaxf(v0, 0.f); v1 = fmaxf(v1, 0.f);
            v2 = fmaxf(v2, 0.f); v3 = fmaxf(v3, 0.f);
        }
        O[(size_t)row * NOUT + col]           = v0;
        O[(size_t)row * NOUT + col + 1]       = v1;
        O[(size_t)(row + 8) * NOUT + col]     = v2;
        O[(size_t)(row + 8) * NOUT + col + 1] = v3;
    }
}

extern "C" void kernel_launch(void* const* d_in, const int* in_sizes, int n_in,
                              void* d_out, int out_size) {
    const float* x   = (const float*)d_in[0];
    const int*   cat = (const int*)  d_in[1];
    const float* W1  = (const float*)d_in[2];
    const float* b1  = (const float*)d_in[3];
    const float* W2  = (const float*)d_in[4];
    const float* b2  = (const float*)d_in[5];
    float*       out = (float*)d_out;

    build_perm_kernel<<<1, 32>>>(cat);

    dim3 grid(B_, HID / 64);
    // Layer 1: x @ W1 + b1, ReLU -> g_hidden
    catmlp_gemm<DIN, true,  false, true ><<<grid, 256>>>(x, W1, b1, cat, nullptr);
    // Layer 2: hidden @ W2 + b2 -> out
    catmlp_gemm<HID, false, true,  false><<<grid, 256>>>(nullptr, W2, b2, cat, out);
}